// round 8
// baseline (speedup 1.0000x reference)
#include <cuda_runtime.h>
#include <cuda_bf16.h>
#include <cstdint>

// CRFConstituency inside-outside, B=8, S=256, lens==255 (fixed triu mask).
// R7: 8-CTA cluster per batch (grid=64), full smem replica of the packed
// inside triangle per CTA. Cross-CTA step barrier = double-buffered remote
// mbarriers (tid0 release-arrives on all 8 peers; everyone acquire-waits on
// the local one) instead of barrier.cluster (saves ~UCGABAR 490cyc/step and
// sleeps instead of spinning). Two alternating mbarriers prevent a
// one-phase-ahead producer from corrupting a slow peer's current phase.

#define SS 256
#define BB 8
#define CLUSTER 8
#define TRI ((SS*(SS-1))/2)          // 32640 floats
#define SMEM_BYTES (TRI*4)           // 130560 bytes dynamic
#define NEGF (-1e30f)

__device__ float g_Ar[BB][SS][SS];
__device__ float g_Ac[BB][SS][SS];

__device__ __forceinline__ int tri_base(int i) {
    return i * (SS - 1) - ((i * (i - 1)) >> 1);
}

__device__ __forceinline__ uint32_t smem_u32(const void* p) {
    uint32_t a;
    asm("{ .reg .u64 t; cvta.to.shared.u64 t, %1; cvt.u32.u64 %0, t; }"
        : "=r"(a) : "l"(p));
    return a;
}

__device__ __forceinline__ void st_peer(uint32_t local_addr, int peer, float v) {
    uint32_t rem;
    asm volatile("mapa.shared::cluster.u32 %0, %1, %2;"
                 : "=r"(rem) : "r"(local_addr), "r"(peer));
    asm volatile("st.shared::cluster.f32 [%0], %1;" :: "r"(rem), "f"(v));
}

__device__ __forceinline__ void mbar_arrive_peer(uint32_t local_mbar, int peer) {
    uint32_t rem;
    asm volatile("mapa.shared::cluster.u32 %0, %1, %2;"
                 : "=r"(rem) : "r"(local_mbar), "r"(peer));
    asm volatile("mbarrier.arrive.release.cluster.shared::cluster.b64 _, [%0];"
                 :: "r"(rem) : "memory");
}

__device__ __forceinline__ void mbar_wait(uint32_t mbar, uint32_t parity) {
    asm volatile(
        "{\n\t"
        ".reg .pred P;\n\t"
        "WAIT_%=:\n\t"
        "mbarrier.try_wait.parity.acquire.cluster.shared::cta.b64 P, [%0], %1, 0x989680;\n\t"
        "@!P bra WAIT_%=;\n\t"
        "}"
        :: "r"(mbar), "r"(parity) : "memory");
}

__device__ __forceinline__ void cluster_sync_all() {
    asm volatile("barrier.cluster.arrive.aligned;" ::: "memory");
    asm volatile("barrier.cluster.wait.aligned;" ::: "memory");
}

__global__ __launch_bounds__(1024, 1) __cluster_dims__(CLUSTER, 1, 1)
void crf_inside_outside_cluster(const float* __restrict__ scores,
                                float* __restrict__ out)
{
    extern __shared__ float s_tri[];     // full packed triangle replica
    __shared__ __align__(8) uint64_t mbars[2];

    const int b = blockIdx.x >> 3;       // cluster index = batch
    uint32_t rank;
    asm("mov.u32 %0, %%cluster_ctarank;" : "=r"(rank));

    const float* sc = scores + b * SS * SS;
    float* mout     = out    + b * SS * SS;

    const int tid  = threadIdx.x;
    const int lane = tid & 31;
    const int wid  = tid >> 5;           // 32 warps
    const int sp_of_warp = wid * CLUSTER + (int)rank;

    const uint32_t mb0 = smem_u32(&mbars[0]);
    const uint32_t mb1 = smem_u32(&mbars[1]);

    if (tid == 0) {
        asm volatile("mbarrier.init.shared.b64 [%0], %1;" :: "r"(mb0), "r"(CLUSTER) : "memory");
        asm volatile("mbarrier.init.shared.b64 [%0], %1;" :: "r"(mb1), "r"(CLUSTER) : "memory");
    }
    // width-1 init of the local replica (local data only)
    for (int i = tid; i < SS - 1; i += blockDim.x)
        s_tri[tri_base(i)] = sc[i * SS + i + 1];
    __syncthreads();
    cluster_sync_all();                  // mbarrier init visible cluster-wide

    int cur = 0;
    int par0 = 0, par1 = 0;

    // step barrier: local sync, tid0 release-arrives on all peers, all wait.
    #define STEP_SYNC()                                                        \
        do {                                                                   \
            __syncthreads();                                                   \
            const uint32_t _mb = cur ? mb1 : mb0;                              \
            if (tid == 0) {                                                    \
                _Pragma("unroll")                                              \
                for (int _p = 0; _p < CLUSTER; ++_p)                           \
                    mbar_arrive_peer(_mb, _p);                                 \
            }                                                                  \
            int& _par = cur ? par1 : par0;                                     \
            mbar_wait(_mb, (uint32_t)_par);                                    \
            _par ^= 1;                                                         \
            cur ^= 1;                                                          \
        } while (0)

    // ---------------- forward widths 2..255 ----------------
    for (int w = 2; w <= SS - 1; ++w) {
        const int nspans = SS - w;
        const int sp = sp_of_warp;
        if (sp < nspans) {
            const int i = sp;
            const int j = i + w;
            const int rb_i = tri_base(i);
            const int nch  = (w - 1 + 31) >> 5;

            const float scij = __ldca(&sc[i * SS + j]);   // hoisted off critical tail

            int k0   = i + 1 + lane;
            int off1 = rb_i + lane;
            int off2 = tri_base(k0) + (j - k0 - 1);
            int kk   = k0;

            float tv[8];
            float mx = NEGF;
            #pragma unroll
            for (int c = 0; c < 8; ++c) {
                tv[c] = NEGF;
                if (c < nch) {
                    if (kk < j)
                        tv[c] = s_tri[off1] + s_tri[off2];
                    off1 += 32;
                    off2 += 7632 - (kk << 5);
                    kk   += 32;
                }
                mx = fmaxf(mx, tv[c]);
            }
            #pragma unroll
            for (int o = 16; o; o >>= 1)
                mx = fmaxf(mx, __shfl_xor_sync(0xffffffffu, mx, o));

            float acc = 0.f;
            #pragma unroll
            for (int c = 0; c < 8; ++c)
                if (c < nch) acc += __expf(tv[c] - mx);
            #pragma unroll
            for (int o = 16; o; o >>= 1)
                acc += __shfl_xor_sync(0xffffffffu, acc, o);

            if (lane == 0) {
                const float val = scij + mx + __logf(acc);
                const uint32_t laddr = smem_u32(&s_tri[rb_i + (j - i - 1)]);
                #pragma unroll
                for (int p = 0; p < CLUSTER; ++p)
                    st_peer(laddr, p, val);
            }
        }
        STEP_SYNC();
    }

    // ---------------- backward init ----------------
    for (int idx = ((int)rank << 13) + tid; idx < (((int)rank + 1) << 13); idx += 1024) {
        const int i = idx >> 8;
        const int j = idx & 255;
        if (j <= i) mout[idx] = 0.f;
    }
    if (rank == 0 && tid == 0) {
        const float s_top = s_tri[tri_base(0) + (SS - 2)];
        mout[SS - 1] = 1.0f;
        const float A = sc[SS - 1] - s_top;      // log g = 0
        __stcg(&g_Ar[b][0][SS - 1], A);
        __stcg(&g_Ac[b][SS - 1][0], A);
    }
    STEP_SYNC();

    // ---------------- backward widths 254..1 ----------------
    // g[a,bc] = sum_{j>bc} exp(s_ab + s[bc,j] + Ar[a][j])
    //         + sum_{i<a}  exp(s_ab + s[i,a]  + Ac[bc][i])
    for (int w = SS - 2; w >= 1; --w) {
        const int nspans = SS - w;
        const int sp = sp_of_warp;
        if (sp < nspans) {
            const int a  = sp;
            const int bc = a + w;
            const float s_ab = s_tri[tri_base(a) + (bc - a - 1)];
            const float scab = __ldca(&sc[a * SS + bc]);

            float acc = 0.f;

            // segment 1: parents (a, j), j = bc+1 .. S-1
            {
                const int rb_bc = tri_base(bc);
                const float* Ar = &g_Ar[b][a][0];
                for (int j = bc + 1 + lane; j < SS; j += 32) {
                    const float x = s_tri[rb_bc + (j - bc - 1)] + __ldcg(Ar + j);
                    acc += __expf(s_ab + x);
                }
            }
            // segment 2: parents (i, bc), i = 0 .. a-1
            {
                const float* Ac = &g_Ac[b][bc][0];
                int i   = lane;
                int off = tri_base(i) + (a - i - 1);
                while (i < a) {
                    acc += __expf(s_ab + s_tri[off] + __ldcg(Ac + i));
                    off += 7632 - (i << 5);
                    i   += 32;
                }
            }

            #pragma unroll
            for (int o = 16; o; o >>= 1)
                acc += __shfl_xor_sync(0xffffffffu, acc, o);

            if (lane == 0) {
                const float g = acc;
                mout[a * SS + bc] = g;
                const float A = __logf(g) + scab - s_ab;
                __stcg(&g_Ar[b][a][bc], A);
                __stcg(&g_Ac[b][bc][a], A);
            }
        }
        STEP_SYNC();
    }
    #undef STEP_SYNC
}

extern "C" void kernel_launch(void* const* d_in, const int* in_sizes, int n_in,
                              void* d_out, int out_size)
{
    (void)in_sizes; (void)n_in; (void)out_size;
    const float* scores = (const float*)d_in[0];
    float* out = (float*)d_out;

    cudaFuncSetAttribute(crf_inside_outside_cluster,
                         cudaFuncAttributeMaxDynamicSharedMemorySize, SMEM_BYTES);
    crf_inside_outside_cluster<<<BB * CLUSTER, 1024, SMEM_BYTES>>>(scores, out);
}

// round 9
// speedup vs baseline: 1.1287x; 1.1287x over previous
#include <cuda_runtime.h>
#include <cuda_bf16.h>
#include <cstdint>

// CRFConstituency inside-outside, B=8, S=256, lens==255 (fixed triu mask).
// R8: R6 compute structure (8-CTA cluster per batch, full smem replica of the
// packed inside triangle per CTA, spans interleaved warp*8+rank, value
// broadcast via st.shared::cluster) with the per-step cluster barrier replaced
// by a monotone epoch-counter barrier:
//   __syncthreads -> warp0 lanes 0..7 release-store epoch into slot[rank] of
//   every peer (one warp instruction) -> every warp's lanes 0..7 acquire-poll
//   the 7 peer slots in LOCAL smem until >= epoch.
// Monotone counters tolerate unbounded producer run-ahead (no parity
// ambiguity); single-writer-per-location data makes run-ahead safe.

#define SS 256
#define BB 8
#define CLUSTER 8
#define TRI ((SS*(SS-1))/2)          // 32640 floats
#define SMEM_BYTES (TRI*4)           // 130560 bytes dynamic
#define NEGF (-1e30f)

__device__ float g_Ar[BB][SS][SS];
__device__ float g_Ac[BB][SS][SS];

__device__ __forceinline__ int tri_base(int i) {
    return i * (SS - 1) - ((i * (i - 1)) >> 1);
}

__device__ __forceinline__ uint32_t smem_u32(const void* p) {
    uint32_t a;
    asm("{ .reg .u64 t; cvta.to.shared.u64 t, %1; cvt.u32.u64 %0, t; }"
        : "=r"(a) : "l"(p));
    return a;
}

__device__ __forceinline__ void st_peer(uint32_t local_addr, int peer, float v) {
    uint32_t rem;
    asm volatile("mapa.shared::cluster.u32 %0, %1, %2;"
                 : "=r"(rem) : "r"(local_addr), "r"(peer));
    asm volatile("st.shared::cluster.f32 [%0], %1;" :: "r"(rem), "f"(v));
}

__device__ __forceinline__ void st_ctr_release(uint32_t local_addr, int peer, uint32_t v) {
    uint32_t rem;
    asm volatile("mapa.shared::cluster.u32 %0, %1, %2;"
                 : "=r"(rem) : "r"(local_addr), "r"(peer));
    asm volatile("st.release.cluster.shared::cluster.u32 [%0], %1;"
                 :: "r"(rem), "r"(v) : "memory");
}

__device__ __forceinline__ uint32_t ld_ctr_acquire(uint32_t addr) {
    uint32_t v;
    asm volatile("ld.acquire.cluster.shared::cta.u32 %0, [%1];"
                 : "=r"(v) : "r"(addr) : "memory");
    return v;
}

__device__ __forceinline__ void cluster_sync_all() {
    asm volatile("barrier.cluster.arrive.aligned;" ::: "memory");
    asm volatile("barrier.cluster.wait.aligned;" ::: "memory");
}

__global__ __launch_bounds__(1024, 1) __cluster_dims__(CLUSTER, 1, 1)
void crf_inside_outside_cluster(const float* __restrict__ scores,
                                float* __restrict__ out)
{
    extern __shared__ float s_tri[];         // full packed triangle replica
    __shared__ __align__(32) uint32_t s_ctr[CLUSTER];   // peer epoch slots

    const int b = blockIdx.x >> 3;           // cluster index = batch
    uint32_t rank;
    asm("mov.u32 %0, %%cluster_ctarank;" : "=r"(rank));

    const float* sc = scores + b * SS * SS;
    float* mout     = out    + b * SS * SS;

    const int tid  = threadIdx.x;
    const int lane = tid & 31;
    const int wid  = tid >> 5;               // 32 warps
    const int sp_of_warp = wid * CLUSTER + (int)rank;

    const uint32_t my_slot_addr  = smem_u32(&s_ctr[rank]);   // slot I write in peers
    const uint32_t lane_slot_addr = smem_u32(&s_ctr[lane & 7]); // slot this lane polls

    // zero counter slots, fill width-1 diagonal of the local replica
    if (tid < CLUSTER) s_ctr[tid] = 0u;
    for (int i = tid; i < SS - 1; i += blockDim.x)
        s_tri[tri_base(i)] = sc[i * SS + i + 1];
    __syncthreads();
    cluster_sync_all();                      // counters zeroed cluster-wide

    uint32_t epoch = 0;

    // step barrier: CTA-local sync; warp0 lanes 0..7 release-store the new
    // epoch into every peer's slot[rank]; all warps' lanes 0..7 acquire-poll
    // the 7 foreign slots locally until they reach the epoch.
    #define STEP_SYNC()                                                        \
        do {                                                                   \
            ++epoch;                                                           \
            __syncthreads();                                                   \
            if (tid < CLUSTER)                                                 \
                st_ctr_release(my_slot_addr, tid, epoch);                      \
            if (lane < CLUSTER && lane != (int)rank) {                         \
                while (ld_ctr_acquire(lane_slot_addr) < epoch) { }             \
            }                                                                  \
            __syncwarp();                                                      \
        } while (0)

    // ---------------- forward widths 2..255 ----------------
    for (int w = 2; w <= SS - 1; ++w) {
        const int nspans = SS - w;
        const int sp = sp_of_warp;
        if (sp < nspans) {
            const int i = sp;
            const int j = i + w;
            const int rb_i = tri_base(i);
            const int nch  = (w - 1 + 31) >> 5;

            const float scij = __ldca(&sc[i * SS + j]);   // hoisted off the tail

            int k0   = i + 1 + lane;
            int off1 = rb_i + lane;
            int off2 = tri_base(k0) + (j - k0 - 1);
            int kk   = k0;

            float tv[8];
            float mx = NEGF;
            #pragma unroll
            for (int c = 0; c < 8; ++c) {
                tv[c] = NEGF;
                if (c < nch) {
                    if (kk < j)
                        tv[c] = s_tri[off1] + s_tri[off2];
                    off1 += 32;
                    off2 += 7632 - (kk << 5);
                    kk   += 32;
                }
                mx = fmaxf(mx, tv[c]);
            }
            #pragma unroll
            for (int o = 16; o; o >>= 1)
                mx = fmaxf(mx, __shfl_xor_sync(0xffffffffu, mx, o));

            float acc = 0.f;
            #pragma unroll
            for (int c = 0; c < 8; ++c)
                if (c < nch) acc += __expf(tv[c] - mx);
            #pragma unroll
            for (int o = 16; o; o >>= 1)
                acc += __shfl_xor_sync(0xffffffffu, acc, o);

            if (lane == 0) {
                const float val = scij + mx + __logf(acc);
                const uint32_t laddr = smem_u32(&s_tri[rb_i + (j - i - 1)]);
                #pragma unroll
                for (int p = 0; p < CLUSTER; ++p)
                    st_peer(laddr, p, val);
            }
        }
        STEP_SYNC();
    }

    // ---------------- backward init ----------------
    for (int idx = ((int)rank << 13) + tid; idx < (((int)rank + 1) << 13); idx += 1024) {
        const int i = idx >> 8;
        const int j = idx & 255;
        if (j <= i) mout[idx] = 0.f;
    }
    if (rank == 0 && tid == 0) {
        const float s_top = s_tri[tri_base(0) + (SS - 2)];
        mout[SS - 1] = 1.0f;
        const float A = sc[SS - 1] - s_top;      // log g = 0
        __stcg(&g_Ar[b][0][SS - 1], A);
        __stcg(&g_Ac[b][SS - 1][0], A);
    }
    STEP_SYNC();

    // ---------------- backward widths 254..1 ----------------
    // g[a,bc] = sum_{j>bc} exp(s_ab + s[bc,j] + Ar[a][j])
    //         + sum_{i<a}  exp(s_ab + s[i,a]  + Ac[bc][i])
    for (int w = SS - 2; w >= 1; --w) {
        const int nspans = SS - w;
        const int sp = sp_of_warp;
        if (sp < nspans) {
            const int a  = sp;
            const int bc = a + w;
            const float s_ab = s_tri[tri_base(a) + (bc - a - 1)];
            const float scab = __ldca(&sc[a * SS + bc]);

            float acc = 0.f;

            // segment 1: parents (a, j), j = bc+1 .. S-1
            {
                const int rb_bc = tri_base(bc);
                const float* Ar = &g_Ar[b][a][0];
                for (int j = bc + 1 + lane; j < SS; j += 32) {
                    const float x = s_tri[rb_bc + (j - bc - 1)] + __ldcg(Ar + j);
                    acc += __expf(s_ab + x);
                }
            }
            // segment 2: parents (i, bc), i = 0 .. a-1
            {
                const float* Ac = &g_Ac[b][bc][0];
                int i   = lane;
                int off = tri_base(i) + (a - i - 1);
                while (i < a) {
                    acc += __expf(s_ab + s_tri[off] + __ldcg(Ac + i));
                    off += 7632 - (i << 5);
                    i   += 32;
                }
            }

            #pragma unroll
            for (int o = 16; o; o >>= 1)
                acc += __shfl_xor_sync(0xffffffffu, acc, o);

            if (lane == 0) {
                const float g = acc;
                mout[a * SS + bc] = g;
                const float A = __logf(g) + scab - s_ab;
                __stcg(&g_Ar[b][a][bc], A);
                __stcg(&g_Ac[b][bc][a], A);
            }
        }
        STEP_SYNC();
    }
    #undef STEP_SYNC
}

extern "C" void kernel_launch(void* const* d_in, const int* in_sizes, int n_in,
                              void* d_out, int out_size)
{
    (void)in_sizes; (void)n_in; (void)out_size;
    const float* scores = (const float*)d_in[0];
    float* out = (float*)d_out;

    cudaFuncSetAttribute(crf_inside_outside_cluster,
                         cudaFuncAttributeMaxDynamicSharedMemorySize, SMEM_BYTES);
    crf_inside_outside_cluster<<<BB * CLUSTER, 1024, SMEM_BYTES>>>(scores, out);
}